// round 8
// baseline (speedup 1.0000x reference)
#include <cuda_runtime.h>
#include <cstdint>

#define BB 4
#define HH 16
#define SSEQ 2048
#define DDIM 64
#define OUT_O_ELEMS ((size_t)BB * HH * SSEQ * DDIM)

#define KC 64
#define NCH (SSEQ / KC)       // 32
#define STQ 68                // Q/K smem stride (floats)
#define STV 72                // V smem stride (floats)

#define SM1_BYTES ((256 * STQ + 2 * KC * STQ) * 4)   // 104448
#define SM2_BYTES (2 * KC * STV * 4)                 // 36864

__device__ int g_maskFlag = 0;
__device__ float g_li[(size_t)BB * HH * SSEQ];       // 512KB scratch: 1/rowsum

__device__ __forceinline__ uint32_t f2tf32(float x) {
    uint32_t r;
    asm("cvt.rna.tf32.f32 %0, %1;" : "=r"(r) : "f"(x));
    return r;
}
__device__ __forceinline__ float tf(float x) { return __uint_as_float(f2tf32(x)); }

__device__ __forceinline__ void mma_tf32(float* c,
                                         uint32_t a0, uint32_t a1, uint32_t a2, uint32_t a3,
                                         uint32_t b0, uint32_t b1) {
    asm volatile(
        "mma.sync.aligned.m16n8k8.row.col.f32.tf32.tf32.f32 "
        "{%0,%1,%2,%3}, {%4,%5,%6,%7}, {%8,%9}, {%0,%1,%2,%3};"
        : "+f"(c[0]), "+f"(c[1]), "+f"(c[2]), "+f"(c[3])
        : "r"(a0), "r"(a1), "r"(a2), "r"(a3), "r"(b0), "r"(b1));
}

__global__ void mask_check(const float* __restrict__ mask, size_t n) {
    size_t i = (size_t)blockIdx.x * blockDim.x + threadIdx.x;
    uint32_t any = 0;
    const size_t stride = (size_t)gridDim.x * blockDim.x;
    for (; i < n; i += stride) any |= __float_as_uint(mask[i]);
    if (__any_sync(0xffffffffu, any != 0u) && (threadIdx.x & 31) == 0)
        atomicOr(&g_maskFlag, 1);
}

// ============================================================
// K1: e = exp(scale*QK^T + mask) -> weights region (unnormalized),
//     g_li = 1/rowsum. 256 q-rows per CTA, 8 warps (warp tile 32 x KC).
// ============================================================
__global__ __launch_bounds__(256, 2)
void qk_exp(const float* __restrict__ q, const float* __restrict__ k,
            const float* __restrict__ mask, float* __restrict__ out) {
    extern __shared__ float sm[];
    float* qS  = sm;                      // 256 x STQ
    float* KS0 = sm + 256 * STQ;          // 64 x STQ
    float* KS1 = KS0 + KC * STQ;

    const int tid = threadIdx.x;
    const int warp = tid >> 5, lane = tid & 31;
    const int grp = lane >> 2, tid4 = lane & 3;
    const int mt = blockIdx.x, bh = blockIdx.y;
    const int q0 = mt * 256;
    const int m0 = warp * 32;
    const size_t base = (size_t)bh * SSEQ * DDIM;
    const int mflag = *(volatile int*)&g_maskFlag;

    // ---- stage Q (pre-scaled 1/8, tf32) ----
    {
        const float4* qg = (const float4*)(q + base + (size_t)q0 * DDIM);
        #pragma unroll
        for (int it = 0; it < 16; it++) {
            int j = tid + it * 256;
            int row = j >> 4, c = (j & 15) * 4;
            float4 v4 = qg[j];
            qS[row * STQ + c]     = tf(v4.x * 0.125f);
            qS[row * STQ + c + 1] = tf(v4.y * 0.125f);
            qS[row * STQ + c + 2] = tf(v4.z * 0.125f);
            qS[row * STQ + c + 3] = tf(v4.w * 0.125f);
        }
    }
    // ---- stage K chunk 0 ----
    {
        const float4* kg = (const float4*)(k + base);
        #pragma unroll
        for (int i = 0; i < 4; i++) {
            int idx = tid + i * 256;
            int row = idx >> 4, c = (idx & 15) * 4;
            float4 a = kg[idx];
            *(float4*)&KS0[row * STQ + c] = make_float4(tf(a.x), tf(a.y), tf(a.z), tf(a.w));
        }
    }
    __syncthreads();

    // ---- gather Q A-fragments into registers ----
    float qa[2][8][4];
    #pragma unroll
    for (int mf = 0; mf < 2; mf++) {
        const int r0 = m0 + mf * 16 + grp;
        #pragma unroll
        for (int kk = 0; kk < 8; kk++) {
            qa[mf][kk][0] = qS[r0 * STQ + kk * 8 + tid4];
            qa[mf][kk][1] = qS[(r0 + 8) * STQ + kk * 8 + tid4];
            qa[mf][kk][2] = qS[r0 * STQ + kk * 8 + tid4 + 4];
            qa[mf][kk][3] = qS[(r0 + 8) * STQ + kk * 8 + tid4 + 4];
        }
    }

    float l[2][2] = {};
    float* wb = out + OUT_O_ELEMS + (size_t)bh * SSEQ * SSEQ + (size_t)q0 * SSEQ;

    for (int c = 0; c < NCH; c++) {
        float* cur = (c & 1) ? KS1 : KS0;
        float* nxt = (c & 1) ? KS0 : KS1;

        float4 pf[4];
        if (c + 1 < NCH) {
            const float4* kg = (const float4*)(k + base + (size_t)(c + 1) * KC * DDIM);
            #pragma unroll
            for (int i = 0; i < 4; i++) pf[i] = kg[tid + i * 256];
        }

        #pragma unroll
        for (int fn = 0; fn < 8; fn++) {
            float s[2][4] = {};
            #pragma unroll
            for (int kk = 0; kk < 8; kk++) {
                uint32_t b0 = __float_as_uint(cur[(fn * 8 + grp) * STQ + kk * 8 + tid4]);
                uint32_t b1 = __float_as_uint(cur[(fn * 8 + grp) * STQ + kk * 8 + tid4 + 4]);
                mma_tf32(s[0], __float_as_uint(qa[0][kk][0]), __float_as_uint(qa[0][kk][1]),
                               __float_as_uint(qa[0][kk][2]), __float_as_uint(qa[0][kk][3]), b0, b1);
                mma_tf32(s[1], __float_as_uint(qa[1][kk][0]), __float_as_uint(qa[1][kk][1]),
                               __float_as_uint(qa[1][kk][2]), __float_as_uint(qa[1][kk][3]), b0, b1);
            }
            #pragma unroll
            for (int mf = 0; mf < 2; mf++) {
                const int r0 = m0 + mf * 16 + grp;
                if (mflag) {
                    const float* mr0 = mask + (size_t)(q0 + r0) * SSEQ + c * KC + fn * 8 + tid4 * 2;
                    const float* mr1 = mr0 + 8 * SSEQ;
                    float2 v0 = *(const float2*)mr0;
                    float2 v1 = *(const float2*)mr1;
                    s[mf][0] += v0.x; s[mf][1] += v0.y; s[mf][2] += v1.x; s[mf][3] += v1.y;
                }
                float e0 = __expf(s[mf][0]), e1 = __expf(s[mf][1]);
                float e2 = __expf(s[mf][2]), e3 = __expf(s[mf][3]);
                float* w0 = wb + (size_t)r0 * SSEQ + c * KC + fn * 8 + tid4 * 2;
                *(float2*)w0 = make_float2(e0, e1);
                *(float2*)(w0 + 8 * SSEQ) = make_float2(e2, e3);
                l[mf][0] += e0 + e1;
                l[mf][1] += e2 + e3;
            }
        }

        if (c + 1 < NCH) {
            #pragma unroll
            for (int i = 0; i < 4; i++) {
                int idx = tid + i * 256;
                int row = idx >> 4, cc = (idx & 15) * 4;
                *(float4*)&nxt[row * STQ + cc] =
                    make_float4(tf(pf[i].x), tf(pf[i].y), tf(pf[i].z), tf(pf[i].w));
            }
        }
        __syncthreads();
    }

    // ---- reduce row sums, write inverse to scratch ----
    #pragma unroll
    for (int mf = 0; mf < 2; mf++)
        #pragma unroll
        for (int i = 0; i < 2; i++) {
            float x = l[mf][i];
            x += __shfl_xor_sync(0xffffffffu, x, 1);
            x += __shfl_xor_sync(0xffffffffu, x, 2);
            if (tid4 == 0)
                g_li[(size_t)bh * SSEQ + q0 + m0 + mf * 16 + grp + i * 8] = 1.f / x;
        }
}

// ============================================================
// K2: read unnormalized e in A-frag layout, scale by li, rewrite
//     final weights in place, PV mma -> O. 256 q-rows/CTA, 8 warps.
// ============================================================
__global__ __launch_bounds__(256, 2)
void pv(const float* __restrict__ v, float* __restrict__ w,
        float* __restrict__ out) {
    extern __shared__ float sm[];
    float* VS0 = sm;               // 64 x STV
    float* VS1 = sm + KC * STV;

    const int tid = threadIdx.x;
    const int warp = tid >> 5, lane = tid & 31;
    const int grp = lane >> 2, tid4 = lane & 3;
    const int mt = blockIdx.x, bh = blockIdx.y;
    const int q0 = mt * 256;
    const int m0 = warp * 32;
    const size_t base = (size_t)bh * SSEQ * DDIM;

    // per-thread row normalizers
    float li[2][2];
    #pragma unroll
    for (int mf = 0; mf < 2; mf++)
        #pragma unroll
        for (int i = 0; i < 2; i++)
            li[mf][i] = g_li[(size_t)bh * SSEQ + q0 + m0 + mf * 16 + grp + i * 8];

    // ---- stage V chunk 0 ----
    {
        const float4* vg = (const float4*)(v + base);
        #pragma unroll
        for (int i = 0; i < 4; i++) {
            int idx = tid + i * 256;
            int row = idx >> 4, c = (idx & 15) * 4;
            float4 a = vg[idx];
            *(float4*)&VS0[row * STV + c] = make_float4(tf(a.x), tf(a.y), tf(a.z), tf(a.w));
        }
    }
    __syncthreads();

    float o[2][8][4] = {};
    float* wp = w + (size_t)bh * SSEQ * SSEQ + (size_t)q0 * SSEQ;

    for (int c = 0; c < NCH; c++) {
        float* cur = (c & 1) ? VS1 : VS0;
        float* nxt = (c & 1) ? VS0 : VS1;

        float4 vpf[4];
        if (c + 1 < NCH) {
            const float4* vg = (const float4*)(v + base + (size_t)(c + 1) * KC * DDIM);
            #pragma unroll
            for (int i = 0; i < 4; i++) vpf[i] = vg[tid + i * 256];
        }

        // software-pipelined P loads (A-fragment layout: col k = tid4 / tid4+4)
        float pc[2][4], pn[2][4];
        #pragma unroll
        for (int mf = 0; mf < 2; mf++) {
            float* pb = wp + (size_t)(m0 + mf * 16 + grp) * SSEQ + c * KC + tid4;
            pc[mf][0] = pb[0];
            pc[mf][1] = pb[8 * SSEQ];
            pc[mf][2] = pb[4];
            pc[mf][3] = pb[4 + 8 * SSEQ];
        }

        #pragma unroll
        for (int fn = 0; fn < 8; fn++) {
            if (fn < 7) {
                #pragma unroll
                for (int mf = 0; mf < 2; mf++) {
                    float* pb = wp + (size_t)(m0 + mf * 16 + grp) * SSEQ + c * KC + (fn + 1) * 8 + tid4;
                    pn[mf][0] = pb[0];
                    pn[mf][1] = pb[8 * SSEQ];
                    pn[mf][2] = pb[4];
                    pn[mf][3] = pb[4 + 8 * SSEQ];
                }
            }
            #pragma unroll
            for (int mf = 0; mf < 2; mf++) {
                float n0 = pc[mf][0] * li[mf][0];
                float n1 = pc[mf][1] * li[mf][1];
                float n2 = pc[mf][2] * li[mf][0];
                float n3 = pc[mf][3] * li[mf][1];

                // rewrite final normalized weights in place
                float* sb = wp + (size_t)(m0 + mf * 16 + grp) * SSEQ + c * KC + fn * 8 + tid4;
                sb[0] = n0;
                sb[8 * SSEQ] = n1;
                sb[4] = n2;
                sb[4 + 8 * SSEQ] = n3;

                uint32_t a0 = f2tf32(n0), a1 = f2tf32(n1);
                uint32_t a2 = f2tf32(n2), a3 = f2tf32(n3);
                #pragma unroll
                for (int nb = 0; nb < 8; nb++) {
                    uint32_t b0 = __float_as_uint(cur[(fn * 8 + tid4) * STV + nb * 8 + grp]);
                    uint32_t b1 = __float_as_uint(cur[(fn * 8 + tid4 + 4) * STV + nb * 8 + grp]);
                    mma_tf32(o[mf][nb], a0, a1, a2, a3, b0, b1);
                }
            }
            #pragma unroll
            for (int mf = 0; mf < 2; mf++)
                #pragma unroll
                for (int i = 0; i < 4; i++) pc[mf][i] = pn[mf][i];
        }

        if (c + 1 < NCH) {
            #pragma unroll
            for (int i = 0; i < 4; i++) {
                int idx = tid + i * 256;
                int row = idx >> 4, cc = (idx & 15) * 4;
                *(float4*)&nxt[row * STV + cc] =
                    make_float4(tf(vpf[i].x), tf(vpf[i].y), tf(vpf[i].z), tf(vpf[i].w));
            }
        }
        __syncthreads();
    }

    // ---- write O ----
    float* ob = out + base + (size_t)q0 * DDIM;
    #pragma unroll
    for (int mf = 0; mf < 2; mf++) {
        const int r0 = m0 + mf * 16 + grp;
        #pragma unroll
        for (int nb = 0; nb < 8; nb++) {
            int col = nb * 8 + tid4 * 2;
            *(float2*)&ob[(size_t)r0 * DDIM + col]       = make_float2(o[mf][nb][0], o[mf][nb][1]);
            *(float2*)&ob[(size_t)(r0 + 8) * DDIM + col] = make_float2(o[mf][nb][2], o[mf][nb][3]);
        }
    }
}

extern "C" void kernel_launch(void* const* d_in, const int* in_sizes, int n_in,
                              void* d_out, int out_size) {
    const float* q    = (const float*)d_in[0];
    const float* k    = (const float*)d_in[1];
    const float* v    = (const float*)d_in[2];
    const float* mask = (const float*)d_in[3];
    float* out = (float*)d_out;
    float* w = out + OUT_O_ELEMS;

    cudaFuncSetAttribute(qk_exp, cudaFuncAttributeMaxDynamicSharedMemorySize, SM1_BYTES);
    cudaFuncSetAttribute(pv,     cudaFuncAttributeMaxDynamicSharedMemorySize, SM2_BYTES);

    mask_check<<<128, 256>>>(mask, (size_t)SSEQ * SSEQ);
    qk_exp<<<dim3(SSEQ / 256, BB * HH), 256, SM1_BYTES>>>(q, k, mask, out);
    pv<<<dim3(SSEQ / 256, BB * HH), 256, SM2_BYTES>>>(v, w, out);
}

// round 9
// speedup vs baseline: 2.9031x; 2.9031x over previous
#include <cuda_runtime.h>
#include <cstdint>

#define BB 4
#define HH 16
#define SSEQ 2048
#define DDIM 64
#define OUT_O_ELEMS ((size_t)BB * HH * SSEQ * DDIM)

#define KC 64
#define NCH (SSEQ / KC)       // 32
#define STQ 68                // Q/K smem stride (floats)
#define STV 72                // V smem stride (floats)
#define STP 68                // P stage stride (floats)

#define SM1_BYTES ((256 * STQ + 2 * KC * STQ) * 4)                  // 104448
// K2: VS0 | VS1 | PS (8 warps x 32 x STP) | liS(256)
#define SM2_FLOATS (2 * KC * STV + 8 * 32 * STP + 256)
#define SM2_BYTES (SM2_FLOATS * 4)                                  // 107520

__device__ int g_maskFlag = 0;
__device__ float g_li[(size_t)BB * HH * SSEQ];   // 1/rowsum scratch (512KB static)

__device__ __forceinline__ uint32_t f2tf32(float x) {
    uint32_t r;
    asm("cvt.rna.tf32.f32 %0, %1;" : "=r"(r) : "f"(x));
    return r;
}
__device__ __forceinline__ float tf(float x) { return __uint_as_float(f2tf32(x)); }

__device__ __forceinline__ void mma_tf32(float* c,
                                         uint32_t a0, uint32_t a1, uint32_t a2, uint32_t a3,
                                         uint32_t b0, uint32_t b1) {
    asm volatile(
        "mma.sync.aligned.m16n8k8.row.col.f32.tf32.tf32.f32 "
        "{%0,%1,%2,%3}, {%4,%5,%6,%7}, {%8,%9}, {%0,%1,%2,%3};"
        : "+f"(c[0]), "+f"(c[1]), "+f"(c[2]), "+f"(c[3])
        : "r"(a0), "r"(a1), "r"(a2), "r"(a3), "r"(b0), "r"(b1));
}

__global__ void mask_check(const float* __restrict__ mask, size_t n) {
    size_t i = (size_t)blockIdx.x * blockDim.x + threadIdx.x;
    uint32_t any = 0;
    const size_t stride = (size_t)gridDim.x * blockDim.x;
    for (; i < n; i += stride) any |= __float_as_uint(mask[i]);
    if (__any_sync(0xffffffffu, any != 0u) && (threadIdx.x & 31) == 0)
        atomicOr(&g_maskFlag, 1);
}

// ============================================================
// K1: e = exp(scale*QK^T + mask) -> weights region (unnormalized),
//     g_li = 1/rowsum. 256 q-rows/CTA, 8 warps (warp tile 32 x KC).
// ============================================================
__global__ __launch_bounds__(256, 2)
void qk_exp(const float* __restrict__ q, const float* __restrict__ k,
            const float* __restrict__ mask, float* __restrict__ out) {
    extern __shared__ float sm[];
    float* qS  = sm;                      // 256 x STQ
    float* KS0 = sm + 256 * STQ;          // 64 x STQ
    float* KS1 = KS0 + KC * STQ;

    const int tid = threadIdx.x;
    const int warp = tid >> 5, lane = tid & 31;
    const int grp = lane >> 2, tid4 = lane & 3;
    const int mt = blockIdx.x, bh = blockIdx.y;
    const int q0 = mt * 256;
    const int m0 = warp * 32;
    const size_t base = (size_t)bh * SSEQ * DDIM;
    const int mflag = *(volatile int*)&g_maskFlag;

    {
        const float4* qg = (const float4*)(q + base + (size_t)q0 * DDIM);
        #pragma unroll
        for (int it = 0; it < 16; it++) {
            int j = tid + it * 256;
            int row = j >> 4, c = (j & 15) * 4;
            float4 v4 = qg[j];
            qS[row * STQ + c]     = tf(v4.x * 0.125f);
            qS[row * STQ + c + 1] = tf(v4.y * 0.125f);
            qS[row * STQ + c + 2] = tf(v4.z * 0.125f);
            qS[row * STQ + c + 3] = tf(v4.w * 0.125f);
        }
    }
    {
        const float4* kg = (const float4*)(k + base);
        #pragma unroll
        for (int i = 0; i < 4; i++) {
            int idx = tid + i * 256;
            int row = idx >> 4, c = (idx & 15) * 4;
            float4 a = kg[idx];
            *(float4*)&KS0[row * STQ + c] = make_float4(tf(a.x), tf(a.y), tf(a.z), tf(a.w));
        }
    }
    __syncthreads();

    float qa[2][8][4];
    #pragma unroll
    for (int mf = 0; mf < 2; mf++) {
        const int r0 = m0 + mf * 16 + grp;
        #pragma unroll
        for (int kk = 0; kk < 8; kk++) {
            qa[mf][kk][0] = qS[r0 * STQ + kk * 8 + tid4];
            qa[mf][kk][1] = qS[(r0 + 8) * STQ + kk * 8 + tid4];
            qa[mf][kk][2] = qS[r0 * STQ + kk * 8 + tid4 + 4];
            qa[mf][kk][3] = qS[(r0 + 8) * STQ + kk * 8 + tid4 + 4];
        }
    }

    float l[2][2] = {};
    float* wb = out + OUT_O_ELEMS + (size_t)bh * SSEQ * SSEQ + (size_t)q0 * SSEQ;

    for (int c = 0; c < NCH; c++) {
        float* cur = (c & 1) ? KS1 : KS0;
        float* nxt = (c & 1) ? KS0 : KS1;

        float4 pf[4];
        if (c + 1 < NCH) {
            const float4* kg = (const float4*)(k + base + (size_t)(c + 1) * KC * DDIM);
            #pragma unroll
            for (int i = 0; i < 4; i++) pf[i] = kg[tid + i * 256];
        }

        #pragma unroll
        for (int fn = 0; fn < 8; fn++) {
            float s[2][4] = {};
            #pragma unroll
            for (int kk = 0; kk < 8; kk++) {
                uint32_t b0 = __float_as_uint(cur[(fn * 8 + grp) * STQ + kk * 8 + tid4]);
                uint32_t b1 = __float_as_uint(cur[(fn * 8 + grp) * STQ + kk * 8 + tid4 + 4]);
                mma_tf32(s[0], __float_as_uint(qa[0][kk][0]), __float_as_uint(qa[0][kk][1]),
                               __float_as_uint(qa[0][kk][2]), __float_as_uint(qa[0][kk][3]), b0, b1);
                mma_tf32(s[1], __float_as_uint(qa[1][kk][0]), __float_as_uint(qa[1][kk][1]),
                               __float_as_uint(qa[1][kk][2]), __float_as_uint(qa[1][kk][3]), b0, b1);
            }
            #pragma unroll
            for (int mf = 0; mf < 2; mf++) {
                const int r0 = m0 + mf * 16 + grp;
                if (mflag) {
                    const float* mr0 = mask + (size_t)(q0 + r0) * SSEQ + c * KC + fn * 8 + tid4 * 2;
                    const float* mr1 = mr0 + 8 * SSEQ;
                    float2 v0 = *(const float2*)mr0;
                    float2 v1 = *(const float2*)mr1;
                    s[mf][0] += v0.x; s[mf][1] += v0.y; s[mf][2] += v1.x; s[mf][3] += v1.y;
                }
                float e0 = __expf(s[mf][0]), e1 = __expf(s[mf][1]);
                float e2 = __expf(s[mf][2]), e3 = __expf(s[mf][3]);
                float* w0 = wb + (size_t)r0 * SSEQ + c * KC + fn * 8 + tid4 * 2;
                *(float2*)w0 = make_float2(e0, e1);
                *(float2*)(w0 + 8 * SSEQ) = make_float2(e2, e3);
                l[mf][0] += e0 + e1;
                l[mf][1] += e2 + e3;
            }
        }

        if (c + 1 < NCH) {
            #pragma unroll
            for (int i = 0; i < 4; i++) {
                int idx = tid + i * 256;
                int row = idx >> 4, cc = (idx & 15) * 4;
                *(float4*)&nxt[row * STQ + cc] =
                    make_float4(tf(pf[i].x), tf(pf[i].y), tf(pf[i].z), tf(pf[i].w));
            }
        }
        __syncthreads();
    }

    #pragma unroll
    for (int mf = 0; mf < 2; mf++)
        #pragma unroll
        for (int i = 0; i < 2; i++) {
            float x = l[mf][i];
            x += __shfl_xor_sync(0xffffffffu, x, 1);
            x += __shfl_xor_sync(0xffffffffu, x, 2);
            if (tid4 == 0)
                g_li[(size_t)bh * SSEQ + q0 + m0 + mf * 16 + grp + i * 8] = 1.f / x;
        }
}

// ============================================================
// K2: per chunk, each warp stages its 32 P-rows coalesced (float4),
// normalizes in flight (write-back coalesced), tf32 copy -> per-warp
// smem tile; PV mma -> O. 256 q-rows/CTA, 8 warps.
// ============================================================
__global__ __launch_bounds__(256, 2)
void pv(const float* __restrict__ v, float* __restrict__ w,
        float* __restrict__ out) {
    extern __shared__ float sm[];
    float* VS0 = sm;                       // 64 x STV
    float* VS1 = VS0 + KC * STV;
    float* PS  = VS1 + KC * STV;           // 8 warps x 32 x STP
    float* liS = PS + 8 * 32 * STP;        // 256

    const int tid = threadIdx.x;
    const int warp = tid >> 5, lane = tid & 31;
    const int grp = lane >> 2, tid4 = lane & 3;
    const int mt = blockIdx.x, bh = blockIdx.y;
    const int q0 = mt * 256;
    const int m0 = warp * 32;
    const size_t base = (size_t)bh * SSEQ * DDIM;

    liS[tid] = g_li[(size_t)bh * SSEQ + q0 + tid];

    // stage V chunk 0
    {
        const float4* vg = (const float4*)(v + base);
        #pragma unroll
        for (int i = 0; i < 4; i++) {
            int idx = tid + i * 256;
            int row = idx >> 4, c = (idx & 15) * 4;
            float4 a = vg[idx];
            *(float4*)&VS0[row * STV + c] = make_float4(tf(a.x), tf(a.y), tf(a.z), tf(a.w));
        }
    }
    __syncthreads();

    float o[2][8][4] = {};
    float* wp = w + (size_t)bh * SSEQ * SSEQ + (size_t)q0 * SSEQ;
    float* pw = PS + warp * 32 * STP;      // this warp's P tile (32 x STP)

    for (int c = 0; c < NCH; c++) {
        float* cur = (c & 1) ? VS1 : VS0;
        float* nxt = (c & 1) ? VS0 : VS1;

        float4 vpf[4];
        if (c + 1 < NCH) {
            const float4* vg = (const float4*)(v + base + (size_t)(c + 1) * KC * DDIM);
            #pragma unroll
            for (int i = 0; i < 4; i++) vpf[i] = vg[tid + i * 256];
        }

        // ---- stage this warp's 32 P rows: load e, normalize, write back, smem ----
        #pragma unroll
        for (int j = 0; j < 16; j++) {
            int idx = lane + j * 32;
            int rl = idx >> 4;               // local row 0..31
            int c4 = (idx & 15) * 4;
            float* gp = wp + (size_t)(m0 + rl) * SSEQ + c * KC + c4;
            float4 e4 = *(float4*)gp;
            float lir = liS[m0 + rl];
            float4 n4 = make_float4(e4.x * lir, e4.y * lir, e4.z * lir, e4.w * lir);
            *(float4*)gp = n4;               // final normalized weights
            *(float4*)&pw[rl * STP + c4] =
                make_float4(tf(n4.x), tf(n4.y), tf(n4.z), tf(n4.w));
        }
        __syncwarp();

        // ---- PV mma ----
        #pragma unroll
        for (int fn = 0; fn < 8; fn++) {
            uint32_t a[2][4];
            #pragma unroll
            for (int mf = 0; mf < 2; mf++) {
                const int r0 = mf * 16 + grp;
                a[mf][0] = __float_as_uint(pw[r0 * STP + fn * 8 + tid4]);
                a[mf][1] = __float_as_uint(pw[(r0 + 8) * STP + fn * 8 + tid4]);
                a[mf][2] = __float_as_uint(pw[r0 * STP + fn * 8 + tid4 + 4]);
                a[mf][3] = __float_as_uint(pw[(r0 + 8) * STP + fn * 8 + tid4 + 4]);
            }
            #pragma unroll
            for (int nb = 0; nb < 8; nb++) {
                uint32_t b0 = __float_as_uint(cur[(fn * 8 + tid4) * STV + nb * 8 + grp]);
                uint32_t b1 = __float_as_uint(cur[(fn * 8 + tid4 + 4) * STV + nb * 8 + grp]);
                mma_tf32(o[0][nb], a[0][0], a[0][1], a[0][2], a[0][3], b0, b1);
                mma_tf32(o[1][nb], a[1][0], a[1][1], a[1][2], a[1][3], b0, b1);
            }
        }

        if (c + 1 < NCH) {
            #pragma unroll
            for (int i = 0; i < 4; i++) {
                int idx = tid + i * 256;
                int row = idx >> 4, cc = (idx & 15) * 4;
                *(float4*)&nxt[row * STV + cc] =
                    make_float4(tf(vpf[i].x), tf(vpf[i].y), tf(vpf[i].z), tf(vpf[i].w));
            }
        }
        __syncthreads();
    }

    // ---- write O ----
    float* ob = out + base + (size_t)q0 * DDIM;
    #pragma unroll
    for (int mf = 0; mf < 2; mf++) {
        const int r0 = q0 >= 0 ? m0 + mf * 16 + grp : 0;
        #pragma unroll
        for (int nb = 0; nb < 8; nb++) {
            int col = nb * 8 + tid4 * 2;
            *(float2*)&ob[(size_t)r0 * DDIM + col]       = make_float2(o[mf][nb][0], o[mf][nb][1]);
            *(float2*)&ob[(size_t)(r0 + 8) * DDIM + col] = make_float2(o[mf][nb][2], o[mf][nb][3]);
        }
    }
}

extern "C" void kernel_launch(void* const* d_in, const int* in_sizes, int n_in,
                              void* d_out, int out_size) {
    const float* q    = (const float*)d_in[0];
    const float* k    = (const float*)d_in[1];
    const float* v    = (const float*)d_in[2];
    const float* mask = (const float*)d_in[3];
    float* out = (float*)d_out;
    float* w = out + OUT_O_ELEMS;

    cudaFuncSetAttribute(qk_exp, cudaFuncAttributeMaxDynamicSharedMemorySize, SM1_BYTES);
    cudaFuncSetAttribute(pv,     cudaFuncAttributeMaxDynamicSharedMemorySize, SM2_BYTES);

    mask_check<<<1024, 256>>>(mask, (size_t)SSEQ * SSEQ);
    qk_exp<<<dim3(SSEQ / 256, BB * HH), 256, SM1_BYTES>>>(q, k, mask, out);
    pv<<<dim3(SSEQ / 256, BB * HH), 256, SM2_BYTES>>>(v, w, out);
}